// round 7
// baseline (speedup 1.0000x reference)
#include <cuda_runtime.h>
#include <cuda_bf16.h>
#include <cuda_fp16.h>
#include <math_constants.h>
#include <cstdint>

#define N_NODES 100000
#define E_EDGES 1600000
#define IN_F    256
#define OUT_F   128
#define ALPHA   0.2f

// ---------------- scratch (static device globals; no allocation) ------------
__device__ __half g_Whh[(size_t)N_NODES * OUT_F];   // 25.6 MB (fp16 Wh)
__device__ float  g_f1[N_NODES];
__device__ float  g_f2[N_NODES];
__device__ float  g_att[E_EDGES];                   // cached logits
__device__ int    g_row_ptr[N_NODES + 1];
__device__ __align__(16) uint8_t g_Bblk[131072];    // blocked bf16 W: hi[64K] lo[64K]

// ---------------- warp-mma helpers (plain sm_103-safe PTX) ------------------
__device__ __forceinline__ uint32_t smem_u32(const void* p) {
    uint32_t a;
    asm("{ .reg .u64 t; cvta.to.shared.u64 t, %1; cvt.u32.u64 %0, t; }"
        : "=r"(a) : "l"(p));
    return a;
}
__device__ __forceinline__ void ldsm_x4(uint32_t* r, uint32_t addr) {
    asm volatile("ldmatrix.sync.aligned.m8n8.x4.shared.b16 {%0,%1,%2,%3}, [%4];"
                 : "=r"(r[0]), "=r"(r[1]), "=r"(r[2]), "=r"(r[3]) : "r"(addr));
}
__device__ __forceinline__ void ldsm_x4_t(uint32_t* r, uint32_t addr) {
    asm volatile("ldmatrix.sync.aligned.m8n8.x4.trans.shared.b16 {%0,%1,%2,%3}, [%4];"
                 : "=r"(r[0]), "=r"(r[1]), "=r"(r[2]), "=r"(r[3]) : "r"(addr));
}
// non-volatile: pure register op, let ptxas schedule freely
__device__ __forceinline__ void mma_bf16(float (&d)[4], const uint32_t* a,
                                         const uint32_t* b) {
    asm("mma.sync.aligned.m16n8k16.row.col.f32.bf16.bf16.f32 "
        "{%0,%1,%2,%3}, {%4,%5,%6,%7}, {%8,%9}, {%0,%1,%2,%3};"
        : "+f"(d[0]), "+f"(d[1]), "+f"(d[2]), "+f"(d[3])
        : "r"(a[0]), "r"(a[1]), "r"(a[2]), "r"(a[3]), "r"(b[0]), "r"(b[1]));
}

// ---------------- K0: CSR row_ptr from sorted row (4 edges/thread) ----------
__global__ void build_row_ptr_kernel(const int* __restrict__ row, int E, int N) {
    int t = blockIdx.x * blockDim.x + threadIdx.x;
    int i0 = t * 4;
    if (i0 >= E) return;
    int prev = (i0 == 0) ? -1 : __ldg(row + i0 - 1);
    if (i0 + 3 < E) {
        int4 r4 = *(const int4*)(row + i0);
        int rr[4] = {r4.x, r4.y, r4.z, r4.w};
        #pragma unroll
        for (int u = 0; u < 4; ++u) {
            int r = rr[u];
            if (r != prev)
                for (int q = prev + 1; q <= r; ++q) g_row_ptr[q] = i0 + u;
            prev = r;
        }
        if (i0 + 4 >= E)
            for (int q = prev + 1; q <= N; ++q) g_row_ptr[q] = E;
    } else {
        for (int u = 0; u < 4 && i0 + u < E; ++u) {
            int r = __ldg(row + i0 + u);
            if (r != prev)
                for (int q = prev + 1; q <= r; ++q) g_row_ptr[q] = i0 + u;
            prev = r;
        }
        for (int q = prev + 1; q <= N; ++q) g_row_ptr[q] = E;
    }
}

// ---------------- K1a: one-time W -> blocked bf16 hi/lo ---------------------
__global__ void convert_B_kernel(const float* __restrict__ Wp) {
    int idx4 = blockIdx.x * 256 + threadIdx.x;   // 0..8191
    int k = idx4 >> 5;
    int n = (idx4 & 31) << 2;
    float4 v = *(const float4*)(Wp + (size_t)k * OUT_F + n);
    __nv_bfloat162 h0 = __floats2bfloat162_rn(v.x, v.y);
    __nv_bfloat162 h1 = __floats2bfloat162_rn(v.z, v.w);
    float2 f0 = __bfloat1622float2(h0);
    float2 f1 = __bfloat1622float2(h1);
    __nv_bfloat162 l0 = __floats2bfloat162_rn(v.x - f0.x, v.y - f0.y);
    __nv_bfloat162 l1 = __floats2bfloat162_rn(v.z - f1.x, v.w - f1.y);
    uint32_t off = (uint32_t)((k >> 4) * 16 + (n >> 3)) * 256
                 + ((k >> 3) & 1) * 128 + (k & 7) * 16 + (n & 7) * 2;
    uint2 uh, ul;
    uh.x = *(uint32_t*)&h0; uh.y = *(uint32_t*)&h1;
    ul.x = *(uint32_t*)&l0; ul.y = *(uint32_t*)&l1;
    *(uint2*)(g_Bblk + off) = uh;
    *(uint2*)(g_Bblk + 65536 + off) = ul;
}

// ---------------- K1b: persistent bf16-split warp-MMA GEMM ------------------
// SMEM: B hi [0,64K) lo [64K,128K); A quarter bufs: buf b at 128K + b*32K,
//       each buf: hi [0,16K) lo [16K,32K)  (128 rows x 64 k, blocked 16x16)
#define SM_B    0
#define SM_A    131072
#define SM_TOTAL 196608

__global__ __launch_bounds__(256, 1)
void gemm_tc_kernel(const float* __restrict__ A,
                    const float* __restrict__ a_src,
                    const float* __restrict__ a_dest, int M, int ntiles) {
    extern __shared__ char smem[];
    uint32_t sb = smem_u32(smem);
    const int tid  = threadIdx.x;
    const int wid  = tid >> 5;
    const int lane = tid & 31;
    const int mw   = wid >> 1;     // 0..3 (M dir)
    const int nw   = wid & 1;      // 0..1 (N dir)

    // ---- load pre-blocked B once per CTA ----
    #pragma unroll
    for (int i = 0; i < 32; ++i)
        *(uint4*)(smem + i * 4096 + tid * 16) =
            *(const uint4*)(g_Bblk + i * 4096 + tid * 16);

    const int arow = tid >> 1;            // 0..127
    const int c0   = (tid & 1) * 32;      // local-k base within quarter

    float4 pf[8];

    for (int tile = blockIdx.x; tile < ntiles; tile += gridDim.x) {
        const int m0g = tile * 128;
        const bool avalid = (m0g + arow) < M;
        const float* aptr = A + (size_t)(m0g + arow) * IN_F + c0;

        float acc[16][4];
        #pragma unroll
        for (int t = 0; t < 16; ++t)
            #pragma unroll
            for (int q = 0; q < 4; ++q) acc[t][q] = 0.f;

        // load quarter 0
        #pragma unroll
        for (int i = 0; i < 8; ++i)
            pf[i] = avalid ? ((const float4*)aptr)[i]
                           : make_float4(0.f, 0.f, 0.f, 0.f);
        // convert+store quarter 0 into buf 0
        {
            char* ab = smem + SM_A;
            #pragma unroll
            for (int i = 0; i < 8; ++i) {
                int kq = c0 + i * 4;
                float4 v = pf[i];
                __nv_bfloat162 h0 = __floats2bfloat162_rn(v.x, v.y);
                __nv_bfloat162 h1 = __floats2bfloat162_rn(v.z, v.w);
                float2 f0 = __bfloat1622float2(h0);
                float2 f1 = __bfloat1622float2(h1);
                __nv_bfloat162 l0 = __floats2bfloat162_rn(v.x - f0.x, v.y - f0.y);
                __nv_bfloat162 l1 = __floats2bfloat162_rn(v.z - f1.x, v.w - f1.y);
                uint32_t off = (uint32_t)((arow >> 4) * 4 + (kq >> 4)) * 512
                             + (((arow >> 3) & 1) + ((kq >> 3) & 1) * 2) * 128
                             + (arow & 7) * 16 + (kq & 7) * 2;
                uint2 uh, ul;
                uh.x = *(uint32_t*)&h0; uh.y = *(uint32_t*)&h1;
                ul.x = *(uint32_t*)&l0; ul.y = *(uint32_t*)&l1;
                *(uint2*)(ab + off) = uh;
                *(uint2*)(ab + 16384 + off) = ul;
            }
        }
        __syncthreads();

        #pragma unroll
        for (int q = 0; q < 4; ++q) {
            // prefetch next quarter (global -> regs), hidden under MMAs
            if (q < 3) {
                const float* src = aptr + (q + 1) * 64;
                #pragma unroll
                for (int i = 0; i < 8; ++i)
                    pf[i] = avalid ? ((const float4*)src)[i]
                                   : make_float4(0.f, 0.f, 0.f, 0.f);
            }
            const uint32_t abase = sb + SM_A + (uint32_t)(q & 1) * 32768;
            #pragma unroll
            for (int kb = 0; kb < 4; ++kb) {
                uint32_t ah0[4], ah1[4], al0[4], al1[4];
                uint32_t at0 = abase + ((uint32_t)((mw * 2 + 0) * 4 + kb) << 9)
                             + (lane << 4);
                uint32_t at1 = abase + ((uint32_t)((mw * 2 + 1) * 4 + kb) << 9)
                             + (lane << 4);
                ldsm_x4(ah0, at0);
                ldsm_x4(ah1, at1);
                ldsm_x4(al0, at0 + 16384);
                ldsm_x4(al1, at1 + 16384);
                int kbg = q * 4 + kb;
                #pragma unroll
                for (int p = 0; p < 4; ++p) {
                    int nb = nw * 8 + p * 2;
                    uint32_t bbase = sb + SM_B + ((uint32_t)(kbg * 16 + nb) << 8)
                                   + (lane << 4);
                    uint32_t bh[4], bl[4];
                    ldsm_x4_t(bh, bbase);
                    ldsm_x4_t(bl, bbase + 65536);
                    // interleaved: dependent MMAs 4 apart
                    mma_bf16(acc[2 * p],         ah0, bh + 0);
                    mma_bf16(acc[8 + 2 * p],     ah1, bh + 0);
                    mma_bf16(acc[2 * p + 1],     ah0, bh + 2);
                    mma_bf16(acc[8 + 2 * p + 1], ah1, bh + 2);
                    mma_bf16(acc[2 * p],         ah0, bl + 0);
                    mma_bf16(acc[8 + 2 * p],     ah1, bl + 0);
                    mma_bf16(acc[2 * p + 1],     ah0, bl + 2);
                    mma_bf16(acc[8 + 2 * p + 1], ah1, bl + 2);
                    mma_bf16(acc[2 * p],         al0, bh + 0);
                    mma_bf16(acc[8 + 2 * p],     al1, bh + 0);
                    mma_bf16(acc[2 * p + 1],     al0, bh + 2);
                    mma_bf16(acc[8 + 2 * p + 1], al1, bh + 2);
                }
            }
            __syncthreads();
            if (q < 3) {
                char* ab = smem + SM_A + ((q + 1) & 1) * 32768;
                #pragma unroll
                for (int i = 0; i < 8; ++i) {
                    int kq = c0 + i * 4;
                    float4 v = pf[i];
                    __nv_bfloat162 h0 = __floats2bfloat162_rn(v.x, v.y);
                    __nv_bfloat162 h1 = __floats2bfloat162_rn(v.z, v.w);
                    float2 f0 = __bfloat1622float2(h0);
                    float2 f1 = __bfloat1622float2(h1);
                    __nv_bfloat162 l0 = __floats2bfloat162_rn(v.x - f0.x, v.y - f0.y);
                    __nv_bfloat162 l1 = __floats2bfloat162_rn(v.z - f1.x, v.w - f1.y);
                    uint32_t off = (uint32_t)((arow >> 4) * 4 + (kq >> 4)) * 512
                                 + (((arow >> 3) & 1) + ((kq >> 3) & 1) * 2) * 128
                                 + (arow & 7) * 16 + (kq & 7) * 2;
                    uint2 uh, ul;
                    uh.x = *(uint32_t*)&h0; uh.y = *(uint32_t*)&h1;
                    ul.x = *(uint32_t*)&l0; ul.y = *(uint32_t*)&l1;
                    *(uint2*)(ab + off) = uh;
                    *(uint2*)(ab + 16384 + off) = ul;
                }
                __syncthreads();
            }
        }

        // ---- epilogue: fp16 Wh + fused f1/f2 scores ----
        float* s1p = (float*)(smem + SM_A);           // [2][128]
        float* s2p = (float*)(smem + SM_A + 1024);    // [2][128]
        const int qr = lane >> 2, qc = lane & 3;

        #pragma unroll
        for (int mt = 0; mt < 2; ++mt) {
            int r0 = mw * 32 + mt * 16 + qr;
            int r1 = r0 + 8;
            float s1a = 0.f, s1b = 0.f, s2a = 0.f, s2b = 0.f;
            #pragma unroll
            for (int nt = 0; nt < 8; ++nt) {
                float* d = acc[mt * 8 + nt];
                int n = nw * 64 + nt * 8 + qc * 2;
                if (m0g + r0 < M)
                    *(__half2*)(g_Whh + (size_t)(m0g + r0) * OUT_F + n)
                        = __floats2half2_rn(d[0], d[1]);
                if (m0g + r1 < M)
                    *(__half2*)(g_Whh + (size_t)(m0g + r1) * OUT_F + n)
                        = __floats2half2_rn(d[2], d[3]);
                float a0 = a_src[n], a1 = a_src[n + 1];
                float b0 = a_dest[n], b1 = a_dest[n + 1];
                s1a += d[0] * a0 + d[1] * a1;
                s1b += d[2] * a0 + d[3] * a1;
                s2a += d[0] * b0 + d[1] * b1;
                s2b += d[2] * b0 + d[3] * b1;
            }
            s1a += __shfl_xor_sync(~0u, s1a, 1); s1a += __shfl_xor_sync(~0u, s1a, 2);
            s1b += __shfl_xor_sync(~0u, s1b, 1); s1b += __shfl_xor_sync(~0u, s1b, 2);
            s2a += __shfl_xor_sync(~0u, s2a, 1); s2a += __shfl_xor_sync(~0u, s2a, 2);
            s2b += __shfl_xor_sync(~0u, s2b, 1); s2b += __shfl_xor_sync(~0u, s2b, 2);
            if (qc == 0) {
                s1p[nw * 128 + r0] = s1a;  s1p[nw * 128 + r1] = s1b;
                s2p[nw * 128 + r0] = s2a;  s2p[nw * 128 + r1] = s2b;
            }
        }
        __syncthreads();
        if (tid < 128) {
            int gm = m0g + tid;
            if (gm < M) {
                g_f1[gm] = s1p[tid] + s1p[128 + tid];
                g_f2[gm] = s2p[tid] + s2p[128 + tid];
            }
        }
        __syncthreads();
    }
}

// ---------------- K2: online softmax + fp16 SpMM + ELU ----------------------
__device__ __forceinline__ float leaky(float x) {
    return x >= 0.f ? x : ALPHA * x;
}

__global__ __launch_bounds__(256)
void aggregate_kernel(const int* __restrict__ col, float* __restrict__ out, int N) {
    int warp = (blockIdx.x * blockDim.x + threadIdx.x) >> 5;
    int lane = threadIdx.x & 31;
    if (warp >= N) return;

    int start = g_row_ptr[warp];
    int end   = g_row_ptr[warp + 1];
    float f1 = g_f1[warp];

    float m = -3.0e38f, d = 0.f;
    for (int j = start + lane; j < end; j += 32) {
        float e = leaky(f1 + g_f2[col[j]]);
        g_att[j] = e;
        float nm = fmaxf(m, e);
        d = d * __expf(m - nm) + __expf(e - nm);
        m = nm;
    }
    #pragma unroll
    for (int o = 16; o; o >>= 1) {
        float mo = __shfl_xor_sync(~0u, m, o);
        float dd = __shfl_xor_sync(~0u, d, o);
        float nm = fmaxf(m, mo);
        d = d * __expf(m - nm) + dd * __expf(mo - nm);
        m = nm;
    }
    float inv = (end > start && d > 0.f) ? 1.f / d : 0.f;
    __syncwarp();

    // fp16 SpMM, unroll x4 for MLP; lane owns features [lane*4, lane*4+4)
    float4 acc = make_float4(0.f, 0.f, 0.f, 0.f);
    int e1i = end - 1;
    for (int j = start; j < end; j += 4) {
        int j1 = min(j + 1, e1i), j2 = min(j + 2, e1i), j3 = min(j + 3, e1i);
        int c0 = col[j], c1 = col[j1], c2 = col[j2], c3 = col[j3];
        float w0 = __expf(g_att[j] - m);
        float w1 = (j + 1 < end) ? __expf(g_att[j1] - m) : 0.f;
        float w2 = (j + 2 < end) ? __expf(g_att[j2] - m) : 0.f;
        float w3 = (j + 3 < end) ? __expf(g_att[j3] - m) : 0.f;
        uint2 u0 = ((const uint2*)(g_Whh + (size_t)c0 * OUT_F))[lane];
        uint2 u1 = ((const uint2*)(g_Whh + (size_t)c1 * OUT_F))[lane];
        uint2 u2 = ((const uint2*)(g_Whh + (size_t)c2 * OUT_F))[lane];
        uint2 u3 = ((const uint2*)(g_Whh + (size_t)c3 * OUT_F))[lane];
        float2 a0 = __half22float2(*(__half2*)&u0.x), b0 = __half22float2(*(__half2*)&u0.y);
        float2 a1 = __half22float2(*(__half2*)&u1.x), b1 = __half22float2(*(__half2*)&u1.y);
        float2 a2 = __half22float2(*(__half2*)&u2.x), b2 = __half22float2(*(__half2*)&u2.y);
        float2 a3 = __half22float2(*(__half2*)&u3.x), b3 = __half22float2(*(__half2*)&u3.y);
        acc.x += w0 * a0.x + w1 * a1.x + w2 * a2.x + w3 * a3.x;
        acc.y += w0 * a0.y + w1 * a1.y + w2 * a2.y + w3 * a3.y;
        acc.z += w0 * b0.x + w1 * b1.x + w2 * b2.x + w3 * b3.x;
        acc.w += w0 * b0.y + w1 * b1.y + w2 * b2.y + w3 * b3.y;
    }
    acc.x *= inv; acc.y *= inv; acc.z *= inv; acc.w *= inv;

    acc.x = acc.x > 0.f ? acc.x : (__expf(acc.x) - 1.f);
    acc.y = acc.y > 0.f ? acc.y : (__expf(acc.y) - 1.f);
    acc.z = acc.z > 0.f ? acc.z : (__expf(acc.z) - 1.f);
    acc.w = acc.w > 0.f ? acc.w : (__expf(acc.w) - 1.f);

    ((float4*)(out + (size_t)warp * OUT_F))[lane] = acc;
}

// ---------------- launch ----------------------------------------------------
extern "C" void kernel_launch(void* const* d_in, const int* in_sizes, int n_in,
                              void* d_out, int out_size) {
    const float* h      = (const float*)d_in[0];
    const float* W      = (const float*)d_in[1];
    const float* a_src  = (const float*)d_in[2];
    const float* a_dest = (const float*)d_in[3];
    const int*   row    = (const int*)d_in[4];
    const int*   col    = (const int*)d_in[5];
    float*       out    = (float*)d_out;

    const int M = in_sizes[0] / IN_F;   // 100000
    const int E = in_sizes[4];          // 1600000
    const int ntiles = (M + 127) / 128; // 782

    cudaFuncSetAttribute(gemm_tc_kernel,
                         cudaFuncAttributeMaxDynamicSharedMemorySize, SM_TOTAL);

    build_row_ptr_kernel<<<(E / 4 + 255) / 256, 256>>>(row, E, M);
    convert_B_kernel<<<32, 256>>>(W);
    gemm_tc_kernel<<<148, 256, SM_TOTAL>>>(h, a_src, a_dest, M, ntiles);
    aggregate_kernel<<<(M + 7) / 8, 256>>>(col, out, M);
}

// round 9
// speedup vs baseline: 1.1799x; 1.1799x over previous
#include <cuda_runtime.h>
#include <cuda_fp16.h>
#include <math_constants.h>
#include <cstdint>

#define N_NODES 100000
#define E_EDGES 1600000
#define IN_F    256
#define OUT_F   128
#define ALPHA   0.2f

// ---------------- scratch (static device globals; no allocation) ------------
__device__ __half g_Whh[(size_t)N_NODES * OUT_F];   // 25.6 MB (fp16 Wh)
__device__ float  g_f1[N_NODES];
__device__ float  g_f2[N_NODES];
__device__ float  g_att[E_EDGES];                   // cached logits
__device__ int    g_row_ptr[N_NODES + 1];
__device__ __align__(16) uint8_t g_Bblk[131072];    // blocked fp16 W: hi[64K] lo[64K]

// ---------------- warp-mma helpers (plain sm_103-safe PTX) ------------------
__device__ __forceinline__ uint32_t smem_u32(const void* p) {
    uint32_t a;
    asm("{ .reg .u64 t; cvta.to.shared.u64 t, %1; cvt.u32.u64 %0, t; }"
        : "=r"(a) : "l"(p));
    return a;
}
__device__ __forceinline__ void ldsm_x4(uint32_t* r, uint32_t addr) {
    asm volatile("ldmatrix.sync.aligned.m8n8.x4.shared.b16 {%0,%1,%2,%3}, [%4];"
                 : "=r"(r[0]), "=r"(r[1]), "=r"(r[2]), "=r"(r[3]) : "r"(addr));
}
__device__ __forceinline__ void ldsm_x4_t(uint32_t* r, uint32_t addr) {
    asm volatile("ldmatrix.sync.aligned.m8n8.x4.trans.shared.b16 {%0,%1,%2,%3}, [%4];"
                 : "=r"(r[0]), "=r"(r[1]), "=r"(r[2]), "=r"(r[3]) : "r"(addr));
}
__device__ __forceinline__ void mma_f16(float (&d)[4], const uint32_t* a,
                                        const uint32_t* b) {
    asm("mma.sync.aligned.m16n8k16.row.col.f32.f16.f16.f32 "
        "{%0,%1,%2,%3}, {%4,%5,%6,%7}, {%8,%9}, {%0,%1,%2,%3};"
        : "+f"(d[0]), "+f"(d[1]), "+f"(d[2]), "+f"(d[3])
        : "r"(a[0]), "r"(a[1]), "r"(a[2]), "r"(a[3]), "r"(b[0]), "r"(b[1]));
}

// ---------------- K0: CSR row_ptr from sorted row (4 edges/thread) ----------
__global__ void build_row_ptr_kernel(const int* __restrict__ row, int E, int N) {
    int t = blockIdx.x * blockDim.x + threadIdx.x;
    int i0 = t * 4;
    if (i0 >= E) return;
    int prev = (i0 == 0) ? -1 : __ldg(row + i0 - 1);
    if (i0 + 3 < E) {
        int4 r4 = *(const int4*)(row + i0);
        int rr[4] = {r4.x, r4.y, r4.z, r4.w};
        #pragma unroll
        for (int u = 0; u < 4; ++u) {
            int r = rr[u];
            if (r != prev)
                for (int q = prev + 1; q <= r; ++q) g_row_ptr[q] = i0 + u;
            prev = r;
        }
        if (i0 + 4 >= E)
            for (int q = prev + 1; q <= N; ++q) g_row_ptr[q] = E;
    } else {
        for (int u = 0; u < 4 && i0 + u < E; ++u) {
            int r = __ldg(row + i0 + u);
            if (r != prev)
                for (int q = prev + 1; q <= r; ++q) g_row_ptr[q] = i0 + u;
            prev = r;
        }
        for (int q = prev + 1; q <= N; ++q) g_row_ptr[q] = E;
    }
}

// ---------------- K1a: one-time W -> blocked fp16 hi/lo ---------------------
__global__ void convert_B_kernel(const float* __restrict__ Wp) {
    int idx4 = blockIdx.x * 256 + threadIdx.x;   // 0..8191
    int k = idx4 >> 5;
    int n = (idx4 & 31) << 2;
    float4 v = *(const float4*)(Wp + (size_t)k * OUT_F + n);
    __half2 h0 = __floats2half2_rn(v.x, v.y);
    __half2 h1 = __floats2half2_rn(v.z, v.w);
    float2 f0 = __half22float2(h0);
    float2 f1 = __half22float2(h1);
    __half2 l0 = __floats2half2_rn(v.x - f0.x, v.y - f0.y);
    __half2 l1 = __floats2half2_rn(v.z - f1.x, v.w - f1.y);
    uint32_t off = (uint32_t)((k >> 4) * 16 + (n >> 3)) * 256
                 + ((k >> 3) & 1) * 128 + (k & 7) * 16 + (n & 7) * 2;
    uint2 uh, ul;
    uh.x = *(uint32_t*)&h0; uh.y = *(uint32_t*)&h1;
    ul.x = *(uint32_t*)&l0; ul.y = *(uint32_t*)&l1;
    *(uint2*)(g_Bblk + off) = uh;
    *(uint2*)(g_Bblk + 65536 + off) = ul;
}

// ---------------- K1b: persistent fp16 warp-MMA GEMM ------------------------
// SMEM: B hi [0,64K) lo [64K,128K); A fp16 full-K tile [128K,192K)
//       A blocked: tile (mb 0..7, kb 0..15) of 16x16 b16 = 512B
#define SM_B    0
#define SM_A    131072
#define SM_TOTAL 196608

__global__ __launch_bounds__(256, 1)
void gemm_tc_kernel(const float* __restrict__ A,
                    const float* __restrict__ a_src,
                    const float* __restrict__ a_dest, int M, int ntiles) {
    extern __shared__ char smem[];
    uint32_t sb = smem_u32(smem);
    const int tid  = threadIdx.x;
    const int wid  = tid >> 5;
    const int lane = tid & 31;
    const int mw   = wid >> 1;     // 0..3 (M dir)
    const int nw   = wid & 1;      // 0..1 (N dir)

    // ---- load pre-blocked B once per CTA ----
    #pragma unroll
    for (int i = 0; i < 32; ++i)
        *(uint4*)(smem + i * 4096 + tid * 16) =
            *(const uint4*)(g_Bblk + i * 4096 + tid * 16);

    const int arow = tid >> 1;            // 0..127
    const int c0   = (tid & 1) * 128;     // k base: thread covers 128 k's

    for (int tile = blockIdx.x; tile < ntiles; tile += gridDim.x) {
        const int m0g = tile * 128;
        const bool avalid = (m0g + arow) < M;
        const float* aptr = A + (size_t)(m0g + arow) * IN_F + c0;

        // ---- convert A tile: 128 rows x 256 k fp32 -> fp16 blocked ----
        #pragma unroll 8
        for (int i = 0; i < 32; ++i) {
            int kq = c0 + i * 4;
            float4 v = avalid ? ((const float4*)aptr)[i]
                              : make_float4(0.f, 0.f, 0.f, 0.f);
            __half2 h0 = __floats2half2_rn(v.x, v.y);
            __half2 h1 = __floats2half2_rn(v.z, v.w);
            uint32_t off = (uint32_t)(((arow >> 4) * 16 + (kq >> 4)) << 9)
                         + ((arow >> 3) & 1) * 128 + ((kq >> 3) & 1) * 256
                         + (arow & 7) * 16 + (kq & 7) * 2;
            uint2 uh;
            uh.x = *(uint32_t*)&h0; uh.y = *(uint32_t*)&h1;
            *(uint2*)(smem + SM_A + off) = uh;
        }
        __syncthreads();

        float acc[16][4];
        #pragma unroll
        for (int t = 0; t < 16; ++t)
            #pragma unroll
            for (int q = 0; q < 4; ++q) acc[t][q] = 0.f;

        // ---- MMA mainloop over 16 k-blocks ----
        #pragma unroll 4
        for (int kb = 0; kb < 16; ++kb) {
            uint32_t ah0[4], ah1[4];
            uint32_t at0 = sb + SM_A + ((uint32_t)((mw * 2 + 0) * 16 + kb) << 9)
                         + (lane << 4);
            uint32_t at1 = sb + SM_A + ((uint32_t)((mw * 2 + 1) * 16 + kb) << 9)
                         + (lane << 4);
            ldsm_x4(ah0, at0);
            ldsm_x4(ah1, at1);
            #pragma unroll
            for (int p = 0; p < 4; ++p) {
                int nb = nw * 8 + p * 2;
                uint32_t bbase = sb + SM_B + ((uint32_t)(kb * 16 + nb) << 8)
                               + (lane << 4);
                uint32_t bh[4], bl[4];
                ldsm_x4_t(bh, bbase);
                ldsm_x4_t(bl, bbase + 65536);
                mma_f16(acc[2 * p],         ah0, bh + 0);
                mma_f16(acc[8 + 2 * p],     ah1, bh + 0);
                mma_f16(acc[2 * p + 1],     ah0, bh + 2);
                mma_f16(acc[8 + 2 * p + 1], ah1, bh + 2);
                mma_f16(acc[2 * p],         ah0, bl + 0);
                mma_f16(acc[8 + 2 * p],     ah1, bl + 0);
                mma_f16(acc[2 * p + 1],     ah0, bl + 2);
                mma_f16(acc[8 + 2 * p + 1], ah1, bl + 2);
            }
        }
        __syncthreads();   // all warps done reading A smem

        // ---- epilogue: fp16 Wh + fused f1/f2 scores (reuse A smem) ----
        float* s1p = (float*)(smem + SM_A);           // [2][128]
        float* s2p = (float*)(smem + SM_A + 1024);    // [2][128]
        const int qr = lane >> 2, qc = lane & 3;

        #pragma unroll
        for (int mt = 0; mt < 2; ++mt) {
            int r0 = mw * 32 + mt * 16 + qr;
            int r1 = r0 + 8;
            float s1a = 0.f, s1b = 0.f, s2a = 0.f, s2b = 0.f;
            #pragma unroll
            for (int nt = 0; nt < 8; ++nt) {
                float* d = acc[mt * 8 + nt];
                int n = nw * 64 + nt * 8 + qc * 2;
                if (m0g + r0 < M)
                    *(__half2*)(g_Whh + (size_t)(m0g + r0) * OUT_F + n)
                        = __floats2half2_rn(d[0], d[1]);
                if (m0g + r1 < M)
                    *(__half2*)(g_Whh + (size_t)(m0g + r1) * OUT_F + n)
                        = __floats2half2_rn(d[2], d[3]);
                float a0 = a_src[n], a1 = a_src[n + 1];
                float b0 = a_dest[n], b1 = a_dest[n + 1];
                s1a += d[0] * a0 + d[1] * a1;
                s1b += d[2] * a0 + d[3] * a1;
                s2a += d[0] * b0 + d[1] * b1;
                s2b += d[2] * b0 + d[3] * b1;
            }
            s1a += __shfl_xor_sync(~0u, s1a, 1); s1a += __shfl_xor_sync(~0u, s1a, 2);
            s1b += __shfl_xor_sync(~0u, s1b, 1); s1b += __shfl_xor_sync(~0u, s1b, 2);
            s2a += __shfl_xor_sync(~0u, s2a, 1); s2a += __shfl_xor_sync(~0u, s2a, 2);
            s2b += __shfl_xor_sync(~0u, s2b, 1); s2b += __shfl_xor_sync(~0u, s2b, 2);
            if (qc == 0) {
                s1p[nw * 128 + r0] = s1a;  s1p[nw * 128 + r1] = s1b;
                s2p[nw * 128 + r0] = s2a;  s2p[nw * 128 + r1] = s2b;
            }
        }
        __syncthreads();
        if (tid < 128) {
            int gm = m0g + tid;
            if (gm < M) {
                g_f1[gm] = s1p[tid] + s1p[128 + tid];
                g_f2[gm] = s2p[tid] + s2p[128 + tid];
            }
        }
        __syncthreads();   // s1p/s2p consumed before next tile overwrites A smem
    }
}

// ---------------- K2: softmax + fp16 SpMM + ELU (one warp per node) ---------
__device__ __forceinline__ float leaky(float x) {
    return x >= 0.f ? x : ALPHA * x;
}

__global__ __launch_bounds__(256)
void aggregate_kernel(const int* __restrict__ col, float* __restrict__ out, int N) {
    int warp = (blockIdx.x * blockDim.x + threadIdx.x) >> 5;
    int lane = threadIdx.x & 31;
    if (warp >= N) return;

    int start = g_row_ptr[warp];
    int end   = g_row_ptr[warp + 1];
    float f1 = g_f1[warp];

    // pass 1: logits + plain max (no expf)
    float m = -3.0e38f;
    for (int j = start + lane; j < end; j += 32) {
        float e = leaky(f1 + g_f2[col[j]]);
        g_att[j] = e;
        m = fmaxf(m, e);
    }
    #pragma unroll
    for (int o = 16; o; o >>= 1)
        m = fmaxf(m, __shfl_xor_sync(~0u, m, o));

    // pass 2: strided weights (1 expf per edge per WARP), broadcast accumulate,
    //         denominator fused into the same loop
    float dsum = 0.f;
    float4 acc = make_float4(0.f, 0.f, 0.f, 0.f);
    for (int j0 = start; j0 < end; j0 += 32) {
        int j = j0 + lane;
        float w = 0.f;
        int cj = 0;
        if (j < end) {
            w = __expf(g_att[j] - m);
            cj = col[j];
        }
        dsum += w;
        int cnt = min(32, end - j0);
        #pragma unroll 4
        for (int u = 0; u < cnt; ++u) {
            float wu = __shfl_sync(~0u, w, u);
            int   cu = __shfl_sync(~0u, cj, u);
            uint2 uv = ((const uint2*)(g_Whh + (size_t)cu * OUT_F))[lane];
            float2 p0 = __half22float2(*(__half2*)&uv.x);
            float2 p1 = __half22float2(*(__half2*)&uv.y);
            acc.x += wu * p0.x;
            acc.y += wu * p0.y;
            acc.z += wu * p1.x;
            acc.w += wu * p1.y;
        }
    }
    #pragma unroll
    for (int o = 16; o; o >>= 1)
        dsum += __shfl_xor_sync(~0u, dsum, o);
    float inv = (end > start && dsum > 0.f) ? 1.f / dsum : 0.f;

    acc.x *= inv; acc.y *= inv; acc.z *= inv; acc.w *= inv;

    acc.x = acc.x > 0.f ? acc.x : (__expf(acc.x) - 1.f);
    acc.y = acc.y > 0.f ? acc.y : (__expf(acc.y) - 1.f);
    acc.z = acc.z > 0.f ? acc.z : (__expf(acc.z) - 1.f);
    acc.w = acc.w > 0.f ? acc.w : (__expf(acc.w) - 1.f);

    ((float4*)(out + (size_t)warp * OUT_F))[lane] = acc;
}

// ---------------- launch ----------------------------------------------------
extern "C" void kernel_launch(void* const* d_in, const int* in_sizes, int n_in,
                              void* d_out, int out_size) {
    const float* h      = (const float*)d_in[0];
    const float* W      = (const float*)d_in[1];
    const float* a_src  = (const float*)d_in[2];
    const float* a_dest = (const float*)d_in[3];
    const int*   row    = (const int*)d_in[4];
    const int*   col    = (const int*)d_in[5];
    float*       out    = (float*)d_out;

    const int M = in_sizes[0] / IN_F;   // 100000
    const int E = in_sizes[4];          // 1600000
    const int ntiles = (M + 127) / 128; // 782

    cudaFuncSetAttribute(gemm_tc_kernel,
                         cudaFuncAttributeMaxDynamicSharedMemorySize, SM_TOTAL);

    build_row_ptr_kernel<<<(E / 4 + 255) / 256, 256>>>(row, E, M);
    convert_B_kernel<<<32, 256>>>(W);
    gemm_tc_kernel<<<148, 256, SM_TOTAL>>>(h, a_src, a_dest, M, ntiles);
    aggregate_kernel<<<(M + 7) / 8, 256>>>(col, out, M);
}

// round 13
// speedup vs baseline: 1.3939x; 1.1814x over previous
#include <cuda_runtime.h>
#include <cuda_fp16.h>
#include <math_constants.h>
#include <cstdint>

#define N_NODES 100000
#define E_EDGES 1600000
#define IN_F    256
#define OUT_F   128
#define ALPHA   0.2f

// ---------------- scratch (static device globals; no allocation) ------------
__device__ __half g_Whh[(size_t)N_NODES * OUT_F];   // 25.6 MB (fp16 Wh)
__device__ float  g_f1[N_NODES];
__device__ float  g_f2[N_NODES];
__device__ float  g_att[E_EDGES];                   // logits (fallback path only)
__device__ int    g_row_ptr[N_NODES + 1];
__device__ __align__(16) uint8_t g_Bblk[65536];     // blocked fp16 W

// ---------------- warp-mma helpers (plain sm_103-safe PTX) ------------------
__device__ __forceinline__ uint32_t smem_u32(const void* p) {
    uint32_t a;
    asm("{ .reg .u64 t; cvta.to.shared.u64 t, %1; cvt.u32.u64 %0, t; }"
        : "=r"(a) : "l"(p));
    return a;
}
__device__ __forceinline__ void ldsm_x4(uint32_t* r, uint32_t addr) {
    asm volatile("ldmatrix.sync.aligned.m8n8.x4.shared.b16 {%0,%1,%2,%3}, [%4];"
                 : "=r"(r[0]), "=r"(r[1]), "=r"(r[2]), "=r"(r[3]) : "r"(addr));
}
__device__ __forceinline__ void ldsm_x4_t(uint32_t* r, uint32_t addr) {
    asm volatile("ldmatrix.sync.aligned.m8n8.x4.trans.shared.b16 {%0,%1,%2,%3}, [%4];"
                 : "=r"(r[0]), "=r"(r[1]), "=r"(r[2]), "=r"(r[3]) : "r"(addr));
}
__device__ __forceinline__ void mma_f16(float (&d)[4], const uint32_t* a,
                                        const uint32_t* b) {
    asm("mma.sync.aligned.m16n8k16.row.col.f32.f16.f16.f32 "
        "{%0,%1,%2,%3}, {%4,%5,%6,%7}, {%8,%9}, {%0,%1,%2,%3};"
        : "+f"(d[0]), "+f"(d[1]), "+f"(d[2]), "+f"(d[3])
        : "r"(a[0]), "r"(a[1]), "r"(a[2]), "r"(a[3]), "r"(b[0]), "r"(b[1]));
}

// ---------------- K0: CSR row_ptr from sorted row (4 edges/thread) ----------
__global__ void build_row_ptr_kernel(const int* __restrict__ row, int E, int N) {
    int t = blockIdx.x * blockDim.x + threadIdx.x;
    int i0 = t * 4;
    if (i0 >= E) return;
    int prev = (i0 == 0) ? -1 : __ldg(row + i0 - 1);
    if (i0 + 3 < E) {
        int4 r4 = *(const int4*)(row + i0);
        int rr[4] = {r4.x, r4.y, r4.z, r4.w};
        #pragma unroll
        for (int u = 0; u < 4; ++u) {
            int r = rr[u];
            if (r != prev)
                for (int q = prev + 1; q <= r; ++q) g_row_ptr[q] = i0 + u;
            prev = r;
        }
        if (i0 + 4 >= E)
            for (int q = prev + 1; q <= N; ++q) g_row_ptr[q] = E;
    } else {
        for (int u = 0; u < 4 && i0 + u < E; ++u) {
            int r = __ldg(row + i0 + u);
            if (r != prev)
                for (int q = prev + 1; q <= r; ++q) g_row_ptr[q] = i0 + u;
            prev = r;
        }
        for (int q = prev + 1; q <= N; ++q) g_row_ptr[q] = E;
    }
}

// ---------------- K1a: one-time W -> blocked fp16 -------------------------
__global__ void convert_B_kernel(const float* __restrict__ Wp) {
    int idx4 = blockIdx.x * 256 + threadIdx.x;   // 0..8191
    int k = idx4 >> 5;
    int n = (idx4 & 31) << 2;
    float4 v = *(const float4*)(Wp + (size_t)k * OUT_F + n);
    __half2 h0 = __floats2half2_rn(v.x, v.y);
    __half2 h1 = __floats2half2_rn(v.z, v.w);
    uint32_t off = (uint32_t)((k >> 4) * 16 + (n >> 3)) * 256
                 + ((k >> 3) & 1) * 128 + (k & 7) * 16 + (n & 7) * 2;
    uint2 uh;
    uh.x = *(uint32_t*)&h0; uh.y = *(uint32_t*)&h1;
    *(uint2*)(g_Bblk + off) = uh;
}

// ---------------- K1b: persistent fp16 warp-MMA GEMM ------------------------
// SMEM: B [0,64K); A fp16 full-K tile [64K,128K)
//       blocked tiles of 16x16 b16 = 512B; B tile (kb, nb) of 16x8 = 256B
#define SM_B    0
#define SM_A    65536
#define SM_TOTAL 131072

__global__ __launch_bounds__(256, 1)
void gemm_tc_kernel(const float* __restrict__ A,
                    const float* __restrict__ a_src,
                    const float* __restrict__ a_dest, int M, int ntiles) {
    extern __shared__ char smem[];
    uint32_t sb = smem_u32(smem);
    const int tid  = threadIdx.x;
    const int wid  = tid >> 5;
    const int lane = tid & 31;
    const int mw   = wid >> 1;     // 0..3 (M dir)
    const int nw   = wid & 1;      // 0..1 (N dir)

    // ---- load pre-blocked B once per CTA ----
    #pragma unroll
    for (int i = 0; i < 16; ++i)
        *(uint4*)(smem + i * 4096 + tid * 16) =
            *(const uint4*)(g_Bblk + i * 4096 + tid * 16);

    const int arow = tid >> 1;            // 0..127
    const int c0   = (tid & 1) * 128;     // k base: thread covers 128 k's

    for (int tile = blockIdx.x; tile < ntiles; tile += gridDim.x) {
        const int m0g = tile * 128;
        const bool avalid = (m0g + arow) < M;
        const float* aptr = A + (size_t)(m0g + arow) * IN_F + c0;

        // ---- convert A tile: 128 rows x 256 k fp32 -> fp16 blocked ----
        #pragma unroll 8
        for (int i = 0; i < 32; ++i) {
            int kq = c0 + i * 4;
            float4 v = avalid ? ((const float4*)aptr)[i]
                              : make_float4(0.f, 0.f, 0.f, 0.f);
            __half2 h0 = __floats2half2_rn(v.x, v.y);
            __half2 h1 = __floats2half2_rn(v.z, v.w);
            uint32_t off = (uint32_t)(((arow >> 4) * 16 + (kq >> 4)) << 9)
                         + ((arow >> 3) & 1) * 128 + ((kq >> 3) & 1) * 256
                         + (arow & 7) * 16 + (kq & 7) * 2;
            uint2 uh;
            uh.x = *(uint32_t*)&h0; uh.y = *(uint32_t*)&h1;
            *(uint2*)(smem + SM_A + off) = uh;
        }
        __syncthreads();

        float acc[16][4];
        #pragma unroll
        for (int t = 0; t < 16; ++t)
            #pragma unroll
            for (int q = 0; q < 4; ++q) acc[t][q] = 0.f;

        // ---- MMA mainloop over 16 k-blocks ----
        #pragma unroll 4
        for (int kb = 0; kb < 16; ++kb) {
            uint32_t ah0[4], ah1[4];
            uint32_t at0 = sb + SM_A + ((uint32_t)((mw * 2 + 0) * 16 + kb) << 9)
                         + (lane << 4);
            uint32_t at1 = sb + SM_A + ((uint32_t)((mw * 2 + 1) * 16 + kb) << 9)
                         + (lane << 4);
            ldsm_x4(ah0, at0);
            ldsm_x4(ah1, at1);
            #pragma unroll
            for (int p = 0; p < 4; ++p) {
                int nb = nw * 8 + p * 2;
                uint32_t bbase = sb + SM_B + ((uint32_t)(kb * 16 + nb) << 8)
                               + (lane << 4);
                uint32_t bh[4];
                ldsm_x4_t(bh, bbase);
                mma_f16(acc[2 * p],         ah0, bh + 0);
                mma_f16(acc[8 + 2 * p],     ah1, bh + 0);
                mma_f16(acc[2 * p + 1],     ah0, bh + 2);
                mma_f16(acc[8 + 2 * p + 1], ah1, bh + 2);
            }
        }
        __syncthreads();   // all warps done reading A smem

        // ---- epilogue: fp16 Wh + fused f1/f2 scores (reuse A smem) ----
        float* s1p = (float*)(smem + SM_A);           // [2][128]
        float* s2p = (float*)(smem + SM_A + 1024);    // [2][128]
        const int qr = lane >> 2, qc = lane & 3;

        #pragma unroll
        for (int mt = 0; mt < 2; ++mt) {
            int r0 = mw * 32 + mt * 16 + qr;
            int r1 = r0 + 8;
            float s1a = 0.f, s1b = 0.f, s2a = 0.f, s2b = 0.f;
            #pragma unroll
            for (int nt = 0; nt < 8; ++nt) {
                float* d = acc[mt * 8 + nt];
                int n = nw * 64 + nt * 8 + qc * 2;
                if (m0g + r0 < M)
                    *(__half2*)(g_Whh + (size_t)(m0g + r0) * OUT_F + n)
                        = __floats2half2_rn(d[0], d[1]);
                if (m0g + r1 < M)
                    *(__half2*)(g_Whh + (size_t)(m0g + r1) * OUT_F + n)
                        = __floats2half2_rn(d[2], d[3]);
                float a0 = a_src[n], a1 = a_src[n + 1];
                float b0 = a_dest[n], b1 = a_dest[n + 1];
                s1a += d[0] * a0 + d[1] * a1;
                s1b += d[2] * a0 + d[3] * a1;
                s2a += d[0] * b0 + d[1] * b1;
                s2b += d[2] * b0 + d[3] * b1;
            }
            s1a += __shfl_xor_sync(~0u, s1a, 1); s1a += __shfl_xor_sync(~0u, s1a, 2);
            s1b += __shfl_xor_sync(~0u, s1b, 1); s1b += __shfl_xor_sync(~0u, s1b, 2);
            s2a += __shfl_xor_sync(~0u, s2a, 1); s2a += __shfl_xor_sync(~0u, s2a, 2);
            s2b += __shfl_xor_sync(~0u, s2b, 1); s2b += __shfl_xor_sync(~0u, s2b, 2);
            if (qc == 0) {
                s1p[nw * 128 + r0] = s1a;  s1p[nw * 128 + r1] = s1b;
                s2p[nw * 128 + r0] = s2a;  s2p[nw * 128 + r1] = s2b;
            }
        }
        __syncthreads();
        if (tid < 128) {
            int gm = m0g + tid;
            if (gm < M) {
                g_f1[gm] = s1p[tid] + s1p[128 + tid];
                g_f2[gm] = s2p[tid] + s2p[128 + tid];
            }
        }
        __syncthreads();   // s1p/s2p consumed before next tile overwrites A smem
    }
}

// ---------------- K2: softmax + fp16 SpMM + ELU (one warp per node) ---------
__device__ __forceinline__ float leaky(float x) {
    return x >= 0.f ? x : ALPHA * x;
}

__global__ __launch_bounds__(256)
void aggregate_kernel(const int* __restrict__ col, float* __restrict__ out, int N) {
    int warp = (blockIdx.x * blockDim.x + threadIdx.x) >> 5;
    int lane = threadIdx.x & 31;
    if (warp >= N) return;

    int start = g_row_ptr[warp];
    int end   = g_row_ptr[warp + 1];
    int deg   = end - start;
    float f1 = g_f1[warp];

    float4 acc = make_float4(0.f, 0.f, 0.f, 0.f);
    float inv = 0.f;

    if (deg <= 32) {
        // fast path: one edge per lane, logit stays in register
        int j = start + lane;
        int cj = 0;
        float e = -3.0e38f;
        if (j < end) {
            cj = col[j];
            e = leaky(f1 + g_f2[cj]);
        }
        float m = e;
        #pragma unroll
        for (int o = 16; o; o >>= 1)
            m = fmaxf(m, __shfl_xor_sync(~0u, m, o));
        float w = (j < end) ? __expf(e - m) : 0.f;
        float dsum = w;
        #pragma unroll
        for (int o = 16; o; o >>= 1)
            dsum += __shfl_xor_sync(~0u, dsum, o);
        inv = (deg > 0 && dsum > 0.f) ? 1.f / dsum : 0.f;

        #pragma unroll 4
        for (int u = 0; u < deg; ++u) {
            float wu = __shfl_sync(~0u, w, u);
            int   cu = __shfl_sync(~0u, cj, u);
            uint2 uv = ((const uint2*)(g_Whh + (size_t)cu * OUT_F))[lane];
            float2 p0 = __half22float2(*(__half2*)&uv.x);
            float2 p1 = __half22float2(*(__half2*)&uv.y);
            acc.x += wu * p0.x;
            acc.y += wu * p0.y;
            acc.z += wu * p1.x;
            acc.w += wu * p1.y;
        }
    } else {
        // fallback: two-pass via g_att cache
        float m = -3.0e38f;
        for (int j = start + lane; j < end; j += 32) {
            float e = leaky(f1 + g_f2[col[j]]);
            g_att[j] = e;
            m = fmaxf(m, e);
        }
        #pragma unroll
        for (int o = 16; o; o >>= 1)
            m = fmaxf(m, __shfl_xor_sync(~0u, m, o));

        float dsum = 0.f;
        for (int j0 = start; j0 < end; j0 += 32) {
            int j = j0 + lane;
            float w = 0.f;
            int cj = 0;
            if (j < end) {
                w = __expf(g_att[j] - m);
                cj = col[j];
            }
            dsum += w;
            int cnt = min(32, end - j0);
            #pragma unroll 4
            for (int u = 0; u < cnt; ++u) {
                float wu = __shfl_sync(~0u, w, u);
                int   cu = __shfl_sync(~0u, cj, u);
                uint2 uv = ((const uint2*)(g_Whh + (size_t)cu * OUT_F))[lane];
                float2 p0 = __half22float2(*(__half2*)&uv.x);
                float2 p1 = __half22float2(*(__half2*)&uv.y);
                acc.x += wu * p0.x;
                acc.y += wu * p0.y;
                acc.z += wu * p1.x;
                acc.w += wu * p1.y;
            }
        }
        #pragma unroll
        for (int o = 16; o; o >>= 1)
            dsum += __shfl_xor_sync(~0u, dsum, o);
        inv = (dsum > 0.f) ? 1.f / dsum : 0.f;
    }

    acc.x *= inv; acc.y *= inv; acc.z *= inv; acc.w *= inv;

    acc.x = acc.x > 0.f ? acc.x : (__expf(acc.x) - 1.f);
    acc.y = acc.y > 0.f ? acc.y : (__expf(acc.y) - 1.f);
    acc.z = acc.z > 0.f ? acc.z : (__expf(acc.z) - 1.f);
    acc.w = acc.w > 0.f ? acc.w : (__expf(acc.w) - 1.f);

    ((float4*)(out + (size_t)warp * OUT_F))[lane] = acc;
}

// ---------------- launch ----------------------------------------------------
extern "C" void kernel_launch(void* const* d_in, const int* in_sizes, int n_in,
                              void* d_out, int out_size) {
    const float* h      = (const float*)d_in[0];
    const float* W      = (const float*)d_in[1];
    const float* a_src  = (const float*)d_in[2];
    const float* a_dest = (const float*)d_in[3];
    const int*   row    = (const int*)d_in[4];
    const int*   col    = (const int*)d_in[5];
    float*       out    = (float*)d_out;

    const int M = in_sizes[0] / IN_F;   // 100000
    const int E = in_sizes[4];          // 1600000
    const int ntiles = (M + 127) / 128; // 782

    cudaFuncSetAttribute(gemm_tc_kernel,
                         cudaFuncAttributeMaxDynamicSharedMemorySize, SM_TOTAL);

    build_row_ptr_kernel<<<(E / 4 + 255) / 256, 256>>>(row, E, M);
    convert_B_kernel<<<32, 256>>>(W);
    gemm_tc_kernel<<<148, 256, SM_TOTAL>>>(h, a_src, a_dest, M, ntiles);
    aggregate_kernel<<<(M + 7) / 8, 256>>>(col, out, M);
}

// round 16
// speedup vs baseline: 1.4933x; 1.0713x over previous
#include <cuda_runtime.h>
#include <cuda_fp16.h>
#include <math_constants.h>
#include <cstdint>

#define N_NODES 100000
#define E_EDGES 1600000
#define IN_F    256
#define OUT_F   128
#define ALPHA   0.2f

// ---------------- scratch (static device globals; no allocation) ------------
__device__ __half g_Whh[(size_t)N_NODES * OUT_F];   // 25.6 MB (fp16 Wh)
__device__ float  g_f1[N_NODES];
__device__ float  g_f2[N_NODES];
__device__ float  g_att[E_EDGES];                   // logits (fallback path only)
__device__ int    g_row_ptr[N_NODES + 1];
__device__ __align__(16) uint8_t g_Bblk[65536];     // blocked fp16 W

// ---------------- warp-mma helpers (plain sm_103-safe PTX) ------------------
__device__ __forceinline__ uint32_t smem_u32(const void* p) {
    uint32_t a;
    asm("{ .reg .u64 t; cvta.to.shared.u64 t, %1; cvt.u32.u64 %0, t; }"
        : "=r"(a) : "l"(p));
    return a;
}
__device__ __forceinline__ void ldsm_x4(uint32_t* r, uint32_t addr) {
    asm volatile("ldmatrix.sync.aligned.m8n8.x4.shared.b16 {%0,%1,%2,%3}, [%4];"
                 : "=r"(r[0]), "=r"(r[1]), "=r"(r[2]), "=r"(r[3]) : "r"(addr));
}
__device__ __forceinline__ void ldsm_x4_t(uint32_t* r, uint32_t addr) {
    asm volatile("ldmatrix.sync.aligned.m8n8.x4.trans.shared.b16 {%0,%1,%2,%3}, [%4];"
                 : "=r"(r[0]), "=r"(r[1]), "=r"(r[2]), "=r"(r[3]) : "r"(addr));
}
__device__ __forceinline__ void mma_f16(float (&d)[4], const uint32_t* a,
                                        const uint32_t* b) {
    asm("mma.sync.aligned.m16n8k16.row.col.f32.f16.f16.f32 "
        "{%0,%1,%2,%3}, {%4,%5,%6,%7}, {%8,%9}, {%0,%1,%2,%3};"
        : "+f"(d[0]), "+f"(d[1]), "+f"(d[2]), "+f"(d[3])
        : "r"(a[0]), "r"(a[1]), "r"(a[2]), "r"(a[3]), "r"(b[0]), "r"(b[1]));
}

// ---------------- K0: CSR row_ptr from sorted row (4 edges/thread) ----------
__global__ void build_row_ptr_kernel(const int* __restrict__ row, int E, int N) {
    int t = blockIdx.x * blockDim.x + threadIdx.x;
    int i0 = t * 4;
    if (i0 >= E) return;
    int prev = (i0 == 0) ? -1 : __ldg(row + i0 - 1);
    if (i0 + 3 < E) {
        int4 r4 = *(const int4*)(row + i0);
        int rr[4] = {r4.x, r4.y, r4.z, r4.w};
        #pragma unroll
        for (int u = 0; u < 4; ++u) {
            int r = rr[u];
            if (r != prev)
                for (int q = prev + 1; q <= r; ++q) g_row_ptr[q] = i0 + u;
            prev = r;
        }
        if (i0 + 4 >= E)
            for (int q = prev + 1; q <= N; ++q) g_row_ptr[q] = E;
    } else {
        for (int u = 0; u < 4 && i0 + u < E; ++u) {
            int r = __ldg(row + i0 + u);
            if (r != prev)
                for (int q = prev + 1; q <= r; ++q) g_row_ptr[q] = i0 + u;
            prev = r;
        }
        for (int q = prev + 1; q <= N; ++q) g_row_ptr[q] = E;
    }
}

// ---------------- K1a: one-time W -> blocked fp16 ---------------------------
__global__ void convert_B_kernel(const float* __restrict__ Wp) {
    int idx4 = blockIdx.x * 256 + threadIdx.x;   // 0..8191
    int k = idx4 >> 5;
    int n = (idx4 & 31) << 2;
    float4 v = *(const float4*)(Wp + (size_t)k * OUT_F + n);
    __half2 h0 = __floats2half2_rn(v.x, v.y);
    __half2 h1 = __floats2half2_rn(v.z, v.w);
    uint32_t off = (uint32_t)((k >> 4) * 16 + (n >> 3)) * 256
                 + ((k >> 3) & 1) * 128 + (k & 7) * 16 + (n & 7) * 2;
    uint2 uh;
    uh.x = *(uint32_t*)&h0; uh.y = *(uint32_t*)&h1;
    *(uint2*)(g_Bblk + off) = uh;
}

// ---------------- K1b: persistent pipelined fp16 warp-MMA GEMM --------------
// SMEM: B [0,64K); A buf0 [64K,128K); A buf1 [128K,192K); scores [192K,+2K)
//       blocked tiles of 16x16 b16 = 512B; B tile (kb, nb) of 16x8 = 256B
#define SM_B    0
#define SM_A0   65536
#define SM_SC   196608
#define SM_TOTAL 198656

__device__ __forceinline__ uint32_t a_blk_off(int arow, int kq) {
    return (uint32_t)(((arow >> 4) * 16 + (kq >> 4)) << 9)
         + ((arow >> 3) & 1) * 128 + ((kq >> 3) & 1) * 256
         + (arow & 7) * 16 + (kq & 7) * 2;
}

__global__ __launch_bounds__(256, 1)
void gemm_tc_kernel(const float* __restrict__ A,
                    const float* __restrict__ a_src,
                    const float* __restrict__ a_dest, int M, int ntiles) {
    extern __shared__ char smem[];
    uint32_t sb = smem_u32(smem);
    const int tid  = threadIdx.x;
    const int wid  = tid >> 5;
    const int lane = tid & 31;
    const int mw   = wid >> 1;     // 0..3 (M dir)
    const int nw   = wid & 1;      // 0..1 (N dir)

    // ---- load pre-blocked B once per CTA ----
    #pragma unroll
    for (int i = 0; i < 16; ++i)
        *(uint4*)(smem + i * 4096 + tid * 16) =
            *(const uint4*)(g_Bblk + i * 4096 + tid * 16);

    const int arow = tid >> 1;            // 0..127
    const int c0   = (tid & 1) * 128;     // k base: thread covers 128 k's

    // ---- convert first tile into buf 0 ----
    int tile = blockIdx.x;
    if (tile < ntiles) {
        const int m0g = tile * 128;
        const bool av = (m0g + arow) < M;
        const float* aptr = A + (size_t)(m0g + arow) * IN_F + c0;
        #pragma unroll 8
        for (int i = 0; i < 32; ++i) {
            float4 v = av ? ((const float4*)aptr)[i]
                          : make_float4(0.f, 0.f, 0.f, 0.f);
            __half2 h0 = __floats2half2_rn(v.x, v.y);
            __half2 h1 = __floats2half2_rn(v.z, v.w);
            uint2 uh;
            uh.x = *(uint32_t*)&h0; uh.y = *(uint32_t*)&h1;
            *(uint2*)(smem + SM_A0 + a_blk_off(arow, c0 + i * 4)) = uh;
        }
    }
    __syncthreads();

    int cur = 0;
    for (; tile < ntiles; tile += gridDim.x) {
        const int m0g = tile * 128;
        const int nt_ = tile + gridDim.x;
        const bool hasnext = nt_ < ntiles;
        const bool nav = hasnext && (nt_ * 128 + arow) < M;
        const float* naptr = A + (size_t)(nt_ * 128 + arow) * IN_F + c0;

        float acc[16][4];
        #pragma unroll
        for (int t = 0; t < 16; ++t)
            #pragma unroll
            for (int q = 0; q < 4; ++q) acc[t][q] = 0.f;

        const uint32_t abase = sb + SM_A0 + (uint32_t)cur * 65536;
        char* nbuf = smem + SM_A0 + (uint32_t)(1 - cur) * 65536;

        // ---- 4 chunks: prefetch next-tile quarter, MMA 4 kb, cvt+STS -------
        #pragma unroll
        for (int q = 0; q < 4; ++q) {
            float4 pf[8];
            if (hasnext) {
                #pragma unroll
                for (int j = 0; j < 8; ++j)
                    pf[j] = nav ? ((const float4*)naptr)[q * 8 + j]
                                : make_float4(0.f, 0.f, 0.f, 0.f);
            }
            #pragma unroll
            for (int kb2 = 0; kb2 < 4; ++kb2) {
                const int kb = q * 4 + kb2;
                uint32_t ah0[4], ah1[4];
                uint32_t at0 = abase + ((uint32_t)((mw * 2 + 0) * 16 + kb) << 9)
                             + (lane << 4);
                uint32_t at1 = abase + ((uint32_t)((mw * 2 + 1) * 16 + kb) << 9)
                             + (lane << 4);
                ldsm_x4(ah0, at0);
                ldsm_x4(ah1, at1);
                #pragma unroll
                for (int p = 0; p < 4; ++p) {
                    int nb = nw * 8 + p * 2;
                    uint32_t bbase = sb + SM_B + ((uint32_t)(kb * 16 + nb) << 8)
                                   + (lane << 4);
                    uint32_t bh[4];
                    ldsm_x4_t(bh, bbase);
                    mma_f16(acc[2 * p],         ah0, bh + 0);
                    mma_f16(acc[8 + 2 * p],     ah1, bh + 0);
                    mma_f16(acc[2 * p + 1],     ah0, bh + 2);
                    mma_f16(acc[8 + 2 * p + 1], ah1, bh + 2);
                }
            }
            if (hasnext) {
                #pragma unroll
                for (int j = 0; j < 8; ++j) {
                    int kq = c0 + q * 32 + j * 4;
                    float4 v = pf[j];
                    __half2 h0 = __floats2half2_rn(v.x, v.y);
                    __half2 h1 = __floats2half2_rn(v.z, v.w);
                    uint2 uh;
                    uh.x = *(uint32_t*)&h0; uh.y = *(uint32_t*)&h1;
                    *(uint2*)(nbuf + a_blk_off(arow, kq)) = uh;
                }
            }
        }

        // ---- epilogue: fp16 Wh + fused f1/f2 scores (dedicated smem) -------
        float* s1p = (float*)(smem + SM_SC);           // [2][128]
        float* s2p = (float*)(smem + SM_SC + 1024);    // [2][128]
        const int qr = lane >> 2, qc = lane & 3;

        #pragma unroll
        for (int mt = 0; mt < 2; ++mt) {
            int r0 = mw * 32 + mt * 16 + qr;
            int r1 = r0 + 8;
            float s1a = 0.f, s1b = 0.f, s2a = 0.f, s2b = 0.f;
            #pragma unroll
            for (int nt = 0; nt < 8; ++nt) {
                float* d = acc[mt * 8 + nt];
                int n = nw * 64 + nt * 8 + qc * 2;
                if (m0g + r0 < M)
                    *(__half2*)(g_Whh + (size_t)(m0g + r0) * OUT_F + n)
                        = __floats2half2_rn(d[0], d[1]);
                if (m0g + r1 < M)
                    *(__half2*)(g_Whh + (size_t)(m0g + r1) * OUT_F + n)
                        = __floats2half2_rn(d[2], d[3]);
                float a0 = a_src[n], a1 = a_src[n + 1];
                float b0 = a_dest[n], b1 = a_dest[n + 1];
                s1a += d[0] * a0 + d[1] * a1;
                s1b += d[2] * a0 + d[3] * a1;
                s2a += d[0] * b0 + d[1] * b1;
                s2b += d[2] * b0 + d[3] * b1;
            }
            s1a += __shfl_xor_sync(~0u, s1a, 1); s1a += __shfl_xor_sync(~0u, s1a, 2);
            s1b += __shfl_xor_sync(~0u, s1b, 1); s1b += __shfl_xor_sync(~0u, s1b, 2);
            s2a += __shfl_xor_sync(~0u, s2a, 1); s2a += __shfl_xor_sync(~0u, s2a, 2);
            s2b += __shfl_xor_sync(~0u, s2b, 1); s2b += __shfl_xor_sync(~0u, s2b, 2);
            if (qc == 0) {
                s1p[nw * 128 + r0] = s1a;  s1p[nw * 128 + r1] = s1b;
                s2p[nw * 128 + r0] = s2a;  s2p[nw * 128 + r1] = s2b;
            }
        }
        __syncthreads();   // scores ready AND next-tile A buffer fully stored
        if (tid < 128) {
            int gm = m0g + tid;
            if (gm < M) {
                g_f1[gm] = s1p[tid] + s1p[128 + tid];
                g_f2[gm] = s2p[tid] + s2p[128 + tid];
            }
        }
        __syncthreads();   // s1p/s2p consumed before next tile overwrites them
        cur ^= 1;
    }
}

// ---------------- K2: softmax + fp16 SpMM + ELU (one warp per node) ---------
__device__ __forceinline__ float leaky(float x) {
    return x >= 0.f ? x : ALPHA * x;
}

__global__ __launch_bounds__(256)
void aggregate_kernel(const int* __restrict__ col, float* __restrict__ out, int N) {
    int warp = (blockIdx.x * blockDim.x + threadIdx.x) >> 5;
    int lane = threadIdx.x & 31;
    if (warp >= N) return;

    int start = g_row_ptr[warp];
    int end   = g_row_ptr[warp + 1];
    int deg   = end - start;
    float f1 = g_f1[warp];

    float4 acc = make_float4(0.f, 0.f, 0.f, 0.f);
    float inv = 0.f;

    if (deg <= 32) {
        // fast path: one edge per lane, logit stays in register
        int j = start + lane;
        int cj = 0;
        float e = -3.0e38f;
        if (j < end) {
            cj = __ldg(col + j);
            e = leaky(f1 + g_f2[cj]);
        }
        float m = e;
        #pragma unroll
        for (int o = 16; o; o >>= 1)
            m = fmaxf(m, __shfl_xor_sync(~0u, m, o));
        float w = (j < end) ? __expf(e - m) : 0.f;
        float dsum = w;
        #pragma unroll
        for (int o = 16; o; o >>= 1)
            dsum += __shfl_xor_sync(~0u, dsum, o);
        inv = (deg > 0 && dsum > 0.f) ? 1.f / dsum : 0.f;

        #pragma unroll 8
        for (int u = 0; u < deg; ++u) {
            float wu = __shfl_sync(~0u, w, u);
            int   cu = __shfl_sync(~0u, cj, u);
            uint2 uv = __ldg(((const uint2*)(g_Whh + (size_t)cu * OUT_F)) + lane);
            float2 p0 = __half22float2(*(__half2*)&uv.x);
            float2 p1 = __half22float2(*(__half2*)&uv.y);
            acc.x += wu * p0.x;
            acc.y += wu * p0.y;
            acc.z += wu * p1.x;
            acc.w += wu * p1.y;
        }
    } else {
        // fallback: two-pass via g_att cache
        float m = -3.0e38f;
        for (int j = start + lane; j < end; j += 32) {
            float e = leaky(f1 + g_f2[col[j]]);
            g_att[j] = e;
            m = fmaxf(m, e);
        }
        #pragma unroll
        for (int o = 16; o; o >>= 1)
            m = fmaxf(m, __shfl_xor_sync(~0u, m, o));

        float dsum = 0.f;
        for (int j0 = start; j0 < end; j0 += 32) {
            int j = j0 + lane;
            float w = 0.f;
            int cj = 0;
            if (j < end) {
                w = __expf(g_att[j] - m);
                cj = __ldg(col + j);
            }
            dsum += w;
            int cnt = min(32, end - j0);
            #pragma unroll 8
            for (int u = 0; u < cnt; ++u) {
                float wu = __shfl_sync(~0u, w, u);
                int   cu = __shfl_sync(~0u, cj, u);
                uint2 uv = __ldg(((const uint2*)(g_Whh + (size_t)cu * OUT_F)) + lane);
                float2 p0 = __half22float2(*(__half2*)&uv.x);
                float2 p1 = __half22float2(*(__half2*)&uv.y);
                acc.x += wu * p0.x;
                acc.y += wu * p0.y;
                acc.z += wu * p1.x;
                acc.w += wu * p1.y;
            }
        }
        #pragma unroll
        for (int o = 16; o; o >>= 1)
            dsum += __shfl_xor_sync(~0u, dsum, o);
        inv = (dsum > 0.f) ? 1.f / dsum : 0.f;
    }

    acc.x *= inv; acc.y *= inv; acc.z *= inv; acc.w *= inv;

    acc.x = acc.x > 0.f ? acc.x : (__expf(acc.x) - 1.f);
    acc.y = acc.y > 0.f ? acc.y : (__expf(acc.y) - 1.f);
    acc.z = acc.z > 0.f ? acc.z : (__expf(acc.z) - 1.f);
    acc.w = acc.w > 0.f ? acc.w : (__expf(acc.w) - 1.f);

    ((float4*)(out + (size_t)warp * OUT_F))[lane] = acc;
}

// ---------------- launch ----------------------------------------------------
extern "C" void kernel_launch(void* const* d_in, const int* in_sizes, int n_in,
                              void* d_out, int out_size) {
    const float* h      = (const float*)d_in[0];
    const float* W      = (const float*)d_in[1];
    const float* a_src  = (const float*)d_in[2];
    const float* a_dest = (const float*)d_in[3];
    const int*   row    = (const int*)d_in[4];
    const int*   col    = (const int*)d_in[5];
    float*       out    = (float*)d_out;

    const int M = in_sizes[0] / IN_F;   // 100000
    const int E = in_sizes[4];          // 1600000
    const int ntiles = (M + 127) / 128; // 782

    cudaFuncSetAttribute(gemm_tc_kernel,
                         cudaFuncAttributeMaxDynamicSharedMemorySize, SM_TOTAL);

    build_row_ptr_kernel<<<(E / 4 + 255) / 256, 256>>>(row, E, M);
    convert_B_kernel<<<32, 256>>>(W);
    gemm_tc_kernel<<<148, 256, SM_TOTAL>>>(h, a_src, a_dest, M, ntiles);
    aggregate_kernel<<<(M + 7) / 8, 256>>>(col, out, M);
}